// round 14
// baseline (speedup 1.0000x reference)
#include <cuda_runtime.h>
#include <math.h>
#include <stdint.h>

// Problem constants (shapes fixed by the dataset)
#define F_IN  512
#define HID   128
#define NCLS  64
#define MAX_N 131072
#define MAX_E 2097152

// ---------------- static device scratch (no allocations allowed) ----------------
__device__ __align__(16) float d_gbuf[(size_t)MAX_N * HID];  // 67 MB
__device__ __align__(16) float d_ybuf[(size_t)MAX_N * HID];  // 67 MB
__device__ float d_dinv[MAX_N];
__device__ int   d_deg[MAX_N];
__device__ int   d_off[MAX_N + 1];
__device__ int   d_cur[MAX_N];
__device__ int   d_csr[MAX_E];
__device__ int   d_bsum[256];
__device__ int   d_boff[256];

// ---------------- f32x2 helpers (base sm_100+ PTX, no 'a'-arch needed) ----------------
__device__ __forceinline__ void fma2(unsigned long long& d, unsigned long long a,
                                     unsigned long long b) {
    asm("fma.rn.f32x2 %0, %1, %2, %0;" : "+l"(d) : "l"(a), "l"(b));
}
__device__ __forceinline__ unsigned long long dup2(float v) {
    unsigned long long r;
    uint32_t u = __float_as_uint(v);
    asm("mov.b64 %0, {%1, %1};" : "=l"(r) : "r"(u));
    return r;
}
__device__ __forceinline__ float2 unpk(unsigned long long p) {
    float2 f;
    asm("mov.b64 {%0, %1}, %2;" : "=f"(f.x), "=f"(f.y) : "l"(p));
    return f;
}

// ---------------- degree / zero ----------------
__global__ void k_zero(int Nn) {
    int i = blockIdx.x * blockDim.x + threadIdx.x;
    if (i < Nn) { d_deg[i] = 0; d_cur[i] = 0; }
}
__global__ void k_count(const int* __restrict__ dst, int Ee) {
    int i = blockIdx.x * blockDim.x + threadIdx.x;
    if (i < Ee) atomicAdd(&d_deg[dst[i]], 1);
}

// ---------------- exclusive scan of d_deg -> d_off (dinv fused into scan1) ----------------
__global__ void k_scan1(int Nn) {
    __shared__ int sh[1024];
    int t = threadIdx.x;
    int i = blockIdx.x * 1024 + t;
    int v = (i < Nn) ? d_deg[i] : 0;
    if (i < Nn) d_dinv[i] = rsqrtf((float)v + 1.0f);   // +1 self loop
    sh[t] = v;
    __syncthreads();
    for (int s = 1; s < 1024; s <<= 1) {
        int x = (t >= s) ? sh[t - s] : 0;
        __syncthreads();
        sh[t] += x;
        __syncthreads();
    }
    if (i < Nn) d_off[i] = sh[t] - v;
    if (t == 1023) d_bsum[blockIdx.x] = sh[1023];
}
__global__ void k_scan2(int nb) {
    int run = 0;
    for (int b = 0; b < nb; b++) { d_boff[b] = run; run += d_bsum[b]; }
}
__global__ void k_scan3(int Nn, int Ee) {
    int i = blockIdx.x * 1024 + threadIdx.x;
    if (i < Nn) d_off[i] += d_boff[blockIdx.x];
    if (i == 0) d_off[Nn] = Ee;
}
__global__ void k_scatter(const int* __restrict__ src, const int* __restrict__ dst, int Ee) {
    int i = blockIdx.x * blockDim.x + threadIdx.x;
    if (i < Ee) {
        int d = dst[i];
        int p = d_off[d] + atomicAdd(&d_cur[d], 1);
        d_csr[p] = src[i];
    }
}

// ============ FFMA2 SGEMM: C[M,128] = A[M,K] @ W[K,128] (+b)(*dinv)(relu) ============
// BM=128, BN=128, BK=16, 256 threads, 8x8 microtile with packed-f32x2 accumulators
// (pairs along n). A stored DUPLICATED in smem so the a-operand is a ready 64-bit
// (v,v) word (broadcast LDS); B pairs come naturally from Ws rows.
#define BKC 16
__global__ __launch_bounds__(256, 2) void k_gemm_f2(
    const float* __restrict__ A, const float* __restrict__ W,
    const float* __restrict__ bias, int useDinv, int doRelu,
    float* __restrict__ Cc, int M, int K)
{
    __shared__ __align__(16) unsigned long long Ad[BKC][128];  // 16 KB (dup pairs)
    __shared__ __align__(16) float Ws[BKC][128];               // 8 KB

    const int tid = threadIdx.x;
    const int tx = tid & 15;          // col group (8 cols each)
    const int ty = tid >> 4;          // row group (8 rows each)
    const int row0 = blockIdx.x * 128;

    unsigned long long acc[8][4];     // acc[i][j2] = (C[i][2j2], C[i][2j2+1])
#pragma unroll
    for (int i = 0; i < 8; i++)
#pragma unroll
        for (int j = 0; j < 4; j++) acc[i][j] = 0ull;

    for (int k0 = 0; k0 < K; k0 += BKC) {
        // ---- A tile: 128 rows x 16 k, transposed + duplicated ----
#pragma unroll
        for (int j = 0; j < 2; j++) {
            int s = tid + j * 256;            // 512 float4 slots
            int r = s >> 2;
            int c4 = (s & 3) << 2;
            int ar = row0 + r;
            float4 v = make_float4(0.f, 0.f, 0.f, 0.f);
            if (ar < M) v = *(const float4*)(A + (size_t)ar * K + k0 + c4);
            Ad[c4 + 0][r] = dup2(v.x);
            Ad[c4 + 1][r] = dup2(v.y);
            Ad[c4 + 2][r] = dup2(v.z);
            Ad[c4 + 3][r] = dup2(v.w);
        }
        // ---- W tile: 16 k x 128 n ----
#pragma unroll
        for (int j = 0; j < 2; j++) {
            int s = tid + j * 256;
            int kr = s >> 5;
            int c4 = (s & 31) << 2;
            *(float4*)&Ws[kr][c4] = *(const float4*)(W + (size_t)(k0 + kr) * 128 + c4);
        }
        __syncthreads();

#pragma unroll
        for (int kk = 0; kk < BKC; kk++) {
            unsigned long long ad[8];
            {
                ulonglong2 t0 = *(const ulonglong2*)&Ad[kk][ty * 8];
                ulonglong2 t1 = *(const ulonglong2*)&Ad[kk][ty * 8 + 2];
                ulonglong2 t2 = *(const ulonglong2*)&Ad[kk][ty * 8 + 4];
                ulonglong2 t3 = *(const ulonglong2*)&Ad[kk][ty * 8 + 6];
                ad[0] = t0.x; ad[1] = t0.y; ad[2] = t1.x; ad[3] = t1.y;
                ad[4] = t2.x; ad[5] = t2.y; ad[6] = t3.x; ad[7] = t3.y;
            }
            unsigned long long bb[4];
            {
                ulonglong2 b0 = *(const ulonglong2*)&Ws[kk][tx * 8];
                ulonglong2 b1 = *(const ulonglong2*)&Ws[kk][tx * 8 + 4];
                bb[0] = b0.x; bb[1] = b0.y; bb[2] = b1.x; bb[3] = b1.y;
            }
#pragma unroll
            for (int i = 0; i < 8; i++)
#pragma unroll
                for (int j = 0; j < 4; j++) fma2(acc[i][j], ad[i], bb[j]);
        }
        __syncthreads();
    }

    float bv[8];
    *(float4*)&bv[0] = *(const float4*)(bias + tx * 8);
    *(float4*)&bv[4] = *(const float4*)(bias + tx * 8 + 4);

#pragma unroll
    for (int i = 0; i < 8; i++) {
        int row = row0 + ty * 8 + i;
        if (row < M) {
            float scale = useDinv ? d_dinv[row] : 1.0f;
            float o[8];
#pragma unroll
            for (int j = 0; j < 4; j++) {
                float2 p = unpk(acc[i][j]);
                o[2 * j]     = (p.x + bv[2 * j])     * scale;
                o[2 * j + 1] = (p.y + bv[2 * j + 1]) * scale;
            }
            if (doRelu) {
#pragma unroll
                for (int j = 0; j < 8; j++) o[j] = fmaxf(o[j], 0.0f);
            }
            *(float4*)(Cc + (size_t)row * 128 + tx * 8)     = *(float4*)&o[0];
            *(float4*)(Cc + (size_t)row * 128 + tx * 8 + 4) = *(float4*)&o[4];
        }
    }
}

// ---------------- CSR aggregation: y[n] = relu(dinv[n]*(g[n] + sum g[src])) ----------------
__global__ void k_aggregate(const float* __restrict__ g, float* __restrict__ y, int Nn) {
    int t = blockIdx.x * blockDim.x + threadIdx.x;
    int node = t >> 5;
    int lane = t & 31;
    if (node >= Nn) return;

    const float* gl = g + lane * 4;
    float4 acc = *(const float4*)(g + (size_t)node * HID + lane * 4);  // self loop term

    int i = d_off[node];
    int e = d_off[node + 1];
    for (; i + 4 <= e; i += 4) {
        int s0 = d_csr[i], s1 = d_csr[i + 1], s2 = d_csr[i + 2], s3 = d_csr[i + 3];
        float4 v0 = *(const float4*)(gl + (size_t)s0 * HID);
        float4 v1 = *(const float4*)(gl + (size_t)s1 * HID);
        float4 v2 = *(const float4*)(gl + (size_t)s2 * HID);
        float4 v3 = *(const float4*)(gl + (size_t)s3 * HID);
        acc.x += v0.x; acc.y += v0.y; acc.z += v0.z; acc.w += v0.w;
        acc.x += v1.x; acc.y += v1.y; acc.z += v1.z; acc.w += v1.w;
        acc.x += v2.x; acc.y += v2.y; acc.z += v2.z; acc.w += v2.w;
        acc.x += v3.x; acc.y += v3.y; acc.z += v3.z; acc.w += v3.w;
    }
    for (; i < e; i++) {
        int s = d_csr[i];
        float4 v = *(const float4*)(gl + (size_t)s * HID);
        acc.x += v.x; acc.y += v.y; acc.z += v.z; acc.w += v.w;
    }

    float dv = d_dinv[node];
    acc.x = fmaxf(acc.x * dv, 0.0f);
    acc.y = fmaxf(acc.y * dv, 0.0f);
    acc.z = fmaxf(acc.z * dv, 0.0f);
    acc.w = fmaxf(acc.w * dv, 0.0f);
    *(float4*)(y + (size_t)node * HID + lane * 4) = acc;
}

// ---------------- fc3 + log_softmax fused: 16 rows x 64 cols per 1024-thread block ----------------
__global__ __launch_bounds__(1024) void k_fc3_lsm(
    const float* __restrict__ yin, const float* __restrict__ W,
    const float* __restrict__ b, float* __restrict__ out, int Nn)
{
    __shared__ float Wsh[HID * NCLS];   // 32 KB
    __shared__ float ysh[16][HID];      // 8 KB
    __shared__ float red[16][NCLS];     // 4 KB

    int tid = threadIdx.x;
    for (int i = tid; i < HID * NCLS; i += 1024) Wsh[i] = W[i];

    int rr = tid >> 6;       // 0..15
    int c  = tid & 63;
    int row = blockIdx.x * 16 + rr;
    bool valid = row < Nn;

    if (valid) {
        ysh[rr][c]      = yin[(size_t)row * HID + c];
        ysh[rr][c + 64] = yin[(size_t)row * HID + 64 + c];
    } else {
        ysh[rr][c] = 0.0f; ysh[rr][c + 64] = 0.0f;
    }
    __syncthreads();

    float z = b[c];
#pragma unroll 8
    for (int k = 0; k < HID; k++) z += ysh[rr][k] * Wsh[k * NCLS + c];

    // row max
    red[rr][c] = z;
    __syncthreads();
    for (int s = 32; s >= 1; s >>= 1) {
        if (c < s) red[rr][c] = fmaxf(red[rr][c], red[rr][c + s]);
        __syncthreads();
    }
    float m = red[rr][0];
    __syncthreads();

    // sum exp
    red[rr][c] = expf(z - m);
    __syncthreads();
    for (int s = 32; s >= 1; s >>= 1) {
        if (c < s) red[rr][c] += red[rr][c + s];
        __syncthreads();
    }
    float lse = logf(red[rr][0]);

    if (valid) out[(size_t)row * NCLS + c] = z - m - lse;
}

// ---------------- launch ----------------
extern "C" void kernel_launch(void* const* d_in, const int* in_sizes, int n_in,
                              void* d_out, int out_size)
{
    const float* x    = (const float*)d_in[0];
    const int*   ei   = (const int*)d_in[1];
    const float* W0   = (const float*)d_in[2];
    const float* b0   = (const float*)d_in[3];
    const float* W1   = (const float*)d_in[4];
    const float* b1   = (const float*)d_in[5];
    const float* W2   = (const float*)d_in[6];
    const float* b2   = (const float*)d_in[7];
    const float* fc1w = (const float*)d_in[8];
    const float* fc1b = (const float*)d_in[9];
    const float* fc2w = (const float*)d_in[10];
    const float* fc2b = (const float*)d_in[11];
    const float* fc3w = (const float*)d_in[12];
    const float* fc3b = (const float*)d_in[13];
    float* out = (float*)d_out;

    const int N = in_sizes[0] / F_IN;
    const int E = in_sizes[1] / 2;
    const int* src = ei;       // edge_index[0]
    const int* dst = ei + E;   // edge_index[1]

    float *g, *y;
    cudaGetSymbolAddress((void**)&g, d_gbuf);
    cudaGetSymbolAddress((void**)&y, d_ybuf);

    const int T = 256;
    int gN  = (N + T - 1) / T;
    int gE  = (E + T - 1) / T;
    int nb  = (N + 1023) / 1024;
    int gM  = (N + 127) / 128;
    int gAg = (N * 32 + T - 1) / T;
    int gFc = (N + 15) / 16;

    // graph structure (dinv fused into scan1); L0 GEMM moved to launch #6 so ncu
    // -s 5 -c 1 lands on a heavy kernel instead of the scan.
    k_zero<<<gN, T>>>(N);                               // 1
    k_count<<<gE, T>>>(dst, E);                         // 2
    k_scan1<<<nb, 1024>>>(N);                           // 3 (also writes d_dinv)
    k_scan2<<<1, 1>>>(nb);                              // 4
    k_scan3<<<nb, 1024>>>(N, E);                        // 5
    // conv0 transform: g = (x@W0+b0)*dinv
    k_gemm_f2<<<gM, T>>>(x, W0, b0, 1, 0, g, N, F_IN);  // 6  <- profiled
    k_scatter<<<gE, T>>>(src, dst, E);                  // 7
    k_aggregate<<<gAg, T>>>(g, y, N);                   // 8
    // conv1
    k_gemm_f2<<<gM, T>>>(y, W1, b1, 1, 0, g, N, HID);
    k_aggregate<<<gAg, T>>>(g, y, N);
    // conv2
    k_gemm_f2<<<gM, T>>>(y, W2, b2, 1, 0, g, N, HID);
    k_aggregate<<<gAg, T>>>(g, y, N);
    // fc1, fc2
    k_gemm_f2<<<gM, T>>>(y, fc1w, fc1b, 0, 1, g, N, HID);
    k_gemm_f2<<<gM, T>>>(g, fc2w, fc2b, 0, 1, y, N, HID);
    // fc3 + log_softmax
    k_fc3_lsm<<<gFc, 1024>>>(y, fc3w, fc3b, out, N);
}

// round 15
// speedup vs baseline: 1.9492x; 1.9492x over previous
#include <cuda_runtime.h>
#include <cuda_bf16.h>
#include <math.h>
#include <stdint.h>

// Problem constants (shapes fixed by the dataset)
#define F_IN  512
#define HID   128
#define NCLS  64
#define MAX_N 131072
#define MAX_E 2097152

// ---------------- static device scratch (no allocations allowed) ----------------
__device__ __align__(16) float d_gbuf[(size_t)MAX_N * HID];  // 67 MB
__device__ __align__(16) float d_ybuf[(size_t)MAX_N * HID];  // 67 MB
__device__ float d_dinv[MAX_N];
__device__ int   d_deg[MAX_N];
__device__ int   d_off[MAX_N + 1];
__device__ int   d_cur[MAX_N];
__device__ int   d_csr[MAX_E];
__device__ int   d_bsum[256];
__device__ int   d_boff[256];

// ================= PTX helpers (plain sm_80-era features) =================
__device__ __forceinline__ uint32_t smem_u32(const void* p) {
    uint32_t a;
    asm("{ .reg .u64 t; cvta.to.shared.u64 t, %1; cvt.u32.u64 %0, t; }" : "=r"(a) : "l"(p));
    return a;
}
__device__ __forceinline__ void ldm_x4(uint32_t* r, uint32_t addr) {
    asm volatile("ldmatrix.sync.aligned.m8n8.x4.shared.b16 {%0,%1,%2,%3}, [%4];"
        : "=r"(r[0]), "=r"(r[1]), "=r"(r[2]), "=r"(r[3]) : "r"(addr));
}
__device__ __forceinline__ void mma16816(float* d, const uint32_t* a, const uint32_t* b) {
    asm volatile("mma.sync.aligned.m16n8k16.row.col.f32.bf16.bf16.f32 "
        "{%0,%1,%2,%3}, {%4,%5,%6,%7}, {%8,%9}, {%0,%1,%2,%3};"
        : "+f"(d[0]), "+f"(d[1]), "+f"(d[2]), "+f"(d[3])
        : "r"(a[0]), "r"(a[1]), "r"(a[2]), "r"(a[3]), "r"(b[0]), "r"(b[1]));
}
// hi/lo bf16 split of a float pair -> packed bf16x2 words
__device__ __forceinline__ void split2(float a, float b, uint32_t& h, uint32_t& l) {
    __nv_bfloat162 hh = __floats2bfloat162_rn(a, b);
    float ra = a - __low2float(hh);
    float rb = b - __high2float(hh);
    __nv_bfloat162 ll = __floats2bfloat162_rn(ra, rb);
    h = *(uint32_t*)&hh;
    l = *(uint32_t*)&ll;
}

// ---------------- degree / zero ----------------
__global__ void k_zero(int Nn) {
    int i = blockIdx.x * blockDim.x + threadIdx.x;
    if (i < Nn) { d_deg[i] = 0; d_cur[i] = 0; }
}
__global__ void k_count(const int* __restrict__ dst, int Ee) {
    int i = blockIdx.x * blockDim.x + threadIdx.x;
    if (i < Ee) atomicAdd(&d_deg[dst[i]], 1);
}

// ---------------- exclusive scan of d_deg -> d_off (dinv fused into scan1) ----------------
__global__ void k_scan1(int Nn) {
    __shared__ int sh[1024];
    int t = threadIdx.x;
    int i = blockIdx.x * 1024 + t;
    int v = (i < Nn) ? d_deg[i] : 0;
    if (i < Nn) d_dinv[i] = rsqrtf((float)v + 1.0f);   // +1 self loop
    sh[t] = v;
    __syncthreads();
    for (int s = 1; s < 1024; s <<= 1) {
        int x = (t >= s) ? sh[t - s] : 0;
        __syncthreads();
        sh[t] += x;
        __syncthreads();
    }
    if (i < Nn) d_off[i] = sh[t] - v;
    if (t == 1023) d_bsum[blockIdx.x] = sh[1023];
}
__global__ void k_scan2(int nb) {
    int run = 0;
    for (int b = 0; b < nb; b++) { d_boff[b] = run; run += d_bsum[b]; }
}
__global__ void k_scan3(int Nn, int Ee) {
    int i = blockIdx.x * 1024 + threadIdx.x;
    if (i < Nn) d_off[i] += d_boff[blockIdx.x];
    if (i == 0) d_off[Nn] = Ee;
}
__global__ void k_scatter(const int* __restrict__ src, const int* __restrict__ dst, int Ee) {
    int i = blockIdx.x * blockDim.x + threadIdx.x;
    if (i < Ee) {
        int d = dst[i];
        int p = d_off[d] + atomicAdd(&d_cur[d], 1);
        d_csr[p] = src[i];
    }
}

// ============ HYBRID GEMM: C[M,128] = A[M,K] @ W[K,128] (+b)(*dinv)(relu) ============
// Even row-tiles: fp32 FFMA path (R5, ~90% of fma-pipe peak).
// Odd  row-tiles: bf16 hi/lo HMMA path (R13, tensor pipe).
// Both pipes run concurrently chip-wide -> rates add.
#define AST 40   // HMMA smem: halfwords per row (32 data + 8 pad); 80B rows
#define SM_BYTES 40960

// ---- fp32 FFMA tile (BK=16, 8x8 microtile) ----
__device__ __forceinline__ void gemm_tile_f32(
    const float* __restrict__ A, const float* __restrict__ W,
    const float* __restrict__ bias, int useDinv, int doRelu,
    float* __restrict__ Cc, int M, int K, int row0, char* smraw)
{
    float (*As)[128] = (float(*)[128])smraw;            // 8 KB
    float (*Ws)[128] = (float(*)[128])(smraw + 8192);   // 8 KB

    const int tid = threadIdx.x;
    const int tx = tid & 15;
    const int ty = tid >> 4;

    float acc[8][8];
#pragma unroll
    for (int i = 0; i < 8; i++)
#pragma unroll
        for (int j = 0; j < 8; j++) acc[i][j] = 0.0f;

    for (int k0 = 0; k0 < K; k0 += 16) {
#pragma unroll
        for (int j = 0; j < 2; j++) {
            int s = tid + j * 256;
            int r = s >> 2;
            int c4 = (s & 3) << 2;
            int arow = row0 + r;
            float4 v = make_float4(0.f, 0.f, 0.f, 0.f);
            if (arow < M) v = *(const float4*)(A + (size_t)arow * K + k0 + c4);
            As[c4 + 0][r] = v.x;
            As[c4 + 1][r] = v.y;
            As[c4 + 2][r] = v.z;
            As[c4 + 3][r] = v.w;
        }
#pragma unroll
        for (int j = 0; j < 2; j++) {
            int s = tid + j * 256;
            int kr = s >> 5;
            int c4 = (s & 31) << 2;
            *(float4*)&Ws[kr][c4] = *(const float4*)(W + (size_t)(k0 + kr) * 128 + c4);
        }
        __syncthreads();

#pragma unroll
        for (int kk = 0; kk < 16; kk++) {
            float a[8], b[8];
            *(float4*)&a[0] = *(const float4*)&As[kk][ty * 8];
            *(float4*)&a[4] = *(const float4*)&As[kk][ty * 8 + 4];
            *(float4*)&b[0] = *(const float4*)&Ws[kk][tx * 8];
            *(float4*)&b[4] = *(const float4*)&Ws[kk][tx * 8 + 4];
#pragma unroll
            for (int i = 0; i < 8; i++)
#pragma unroll
                for (int j = 0; j < 8; j++) acc[i][j] += a[i] * b[j];
        }
        __syncthreads();
    }

    float bv[8];
    *(float4*)&bv[0] = *(const float4*)(bias + tx * 8);
    *(float4*)&bv[4] = *(const float4*)(bias + tx * 8 + 4);

#pragma unroll
    for (int i = 0; i < 8; i++) {
        int row = row0 + ty * 8 + i;
        if (row < M) {
            float scale = useDinv ? d_dinv[row] : 1.0f;
            float o[8];
#pragma unroll
            for (int j = 0; j < 8; j++) {
                float v = (acc[i][j] + bv[j]) * scale;
                if (doRelu) v = fmaxf(v, 0.0f);
                o[j] = v;
            }
            *(float4*)(Cc + (size_t)row * 128 + tx * 8)     = *(float4*)&o[0];
            *(float4*)(Cc + (size_t)row * 128 + tx * 8 + 4) = *(float4*)&o[4];
        }
    }
}

// ---- bf16 hi/lo HMMA tile (BK=32, warp tile 32x64) ----
__device__ __forceinline__ void gemm_tile_mma(
    const float* __restrict__ A, const float* __restrict__ W,
    const float* __restrict__ bias, int useDinv, int doRelu,
    float* __restrict__ C, int M, int K, int row0, char* smraw)
{
    __nv_bfloat16* sAh = (__nv_bfloat16*)smraw;                // 10240 B each
    __nv_bfloat16* sAl = (__nv_bfloat16*)(smraw + 10240);
    __nv_bfloat16* sBh = (__nv_bfloat16*)(smraw + 20480);      // stored [n][k]
    __nv_bfloat16* sBl = (__nv_bfloat16*)(smraw + 30720);

    const int tid  = threadIdx.x;
    const int lane = tid & 31;
    const int warp = tid >> 5;
    const int wm = (warp & 3) * 32;
    const int wn = (warp >> 2) * 64;

    const uint32_t uAh = smem_u32(sAh), uAl = smem_u32(sAl);
    const uint32_t uBh = smem_u32(sBh), uBl = smem_u32(sBl);

    const uint32_t aoff = (uint32_t)(((wm + (lane & 15)) * AST + (lane >> 4) * 8) * 2);
    const uint32_t boff = (uint32_t)(((wn + (lane & 7) + ((lane >> 4) & 1) * 8) * AST
                                      + ((lane >> 3) & 1) * 8) * 2);

    float acc[2][8][4];
#pragma unroll
    for (int mb = 0; mb < 2; mb++)
#pragma unroll
        for (int nb = 0; nb < 8; nb++)
#pragma unroll
            for (int q = 0; q < 4; q++) acc[mb][nb][q] = 0.0f;

    for (int k0 = 0; k0 < K; k0 += 32) {
#pragma unroll
        for (int j = 0; j < 4; j++) {
            int i = tid + j * 256;
            int r = i >> 3;
            int c4 = (i & 7) << 2;
            int gr = row0 + r;
            float4 v = make_float4(0.f, 0.f, 0.f, 0.f);
            if (gr < M) v = *(const float4*)(A + (size_t)gr * K + k0 + c4);
            uint32_t h0, l0, h1, l1;
            split2(v.x, v.y, h0, l0);
            split2(v.z, v.w, h1, l1);
            int o = r * AST + c4;
            *(uint2*)(sAh + o) = make_uint2(h0, h1);
            *(uint2*)(sAl + o) = make_uint2(l0, l1);
        }
#pragma unroll
        for (int j = 0; j < 8; j++) {
            int i = tid + j * 256;
            int kk = i >> 7;
            int n  = i & 127;
            float w0 = W[(size_t)(k0 + 2 * kk)     * 128 + n];
            float w1 = W[(size_t)(k0 + 2 * kk + 1) * 128 + n];
            uint32_t h, l;
            split2(w0, w1, h, l);
            int o = n * AST + 2 * kk;
            *(uint32_t*)(sBh + o) = h;
            *(uint32_t*)(sBl + o) = l;
        }
        __syncthreads();

#pragma unroll
        for (int ks = 0; ks < 32; ks += 16) {
            const uint32_t ksb = (uint32_t)(ks * 2);
            uint32_t ah[2][4], al[2][4], bf[8][2];

            ldm_x4(ah[0], uAh + aoff + ksb);
            ldm_x4(ah[1], uAh + aoff + ksb + 16 * AST * 2);
#pragma unroll
            for (int nb4 = 0; nb4 < 4; nb4++) {
                uint32_t r4[4];
                ldm_x4(r4, uBh + boff + ksb + nb4 * 16 * AST * 2);
                bf[2 * nb4][0] = r4[0]; bf[2 * nb4][1] = r4[1];
                bf[2 * nb4 + 1][0] = r4[2]; bf[2 * nb4 + 1][1] = r4[3];
            }
#pragma unroll
            for (int mb = 0; mb < 2; mb++)
#pragma unroll
                for (int nb = 0; nb < 8; nb++) mma16816(acc[mb][nb], ah[mb], bf[nb]);

            ldm_x4(al[0], uAl + aoff + ksb);
            ldm_x4(al[1], uAl + aoff + ksb + 16 * AST * 2);
#pragma unroll
            for (int mb = 0; mb < 2; mb++)
#pragma unroll
                for (int nb = 0; nb < 8; nb++) mma16816(acc[mb][nb], al[mb], bf[nb]);

#pragma unroll
            for (int nb4 = 0; nb4 < 4; nb4++) {
                uint32_t r4[4];
                ldm_x4(r4, uBl + boff + ksb + nb4 * 16 * AST * 2);
                bf[2 * nb4][0] = r4[0]; bf[2 * nb4][1] = r4[1];
                bf[2 * nb4 + 1][0] = r4[2]; bf[2 * nb4 + 1][1] = r4[3];
            }
#pragma unroll
            for (int mb = 0; mb < 2; mb++)
#pragma unroll
                for (int nb = 0; nb < 8; nb++) mma16816(acc[mb][nb], ah[mb], bf[nb]);
        }
        __syncthreads();
    }

#pragma unroll
    for (int mb = 0; mb < 2; mb++) {
        int r0 = row0 + wm + mb * 16 + (lane >> 2);
        int r1 = r0 + 8;
        float s0 = 1.0f, s1 = 1.0f;
        if (useDinv) {
            if (r0 < M) s0 = d_dinv[r0];
            if (r1 < M) s1 = d_dinv[r1];
        }
#pragma unroll
        for (int nb = 0; nb < 8; nb++) {
            int c = wn + nb * 8 + (lane & 3) * 2;
            float2 bv = *(const float2*)(bias + c);
            float v0 = (acc[mb][nb][0] + bv.x) * s0;
            float v1 = (acc[mb][nb][1] + bv.y) * s0;
            float v2 = (acc[mb][nb][2] + bv.x) * s1;
            float v3 = (acc[mb][nb][3] + bv.y) * s1;
            if (doRelu) {
                v0 = fmaxf(v0, 0.f); v1 = fmaxf(v1, 0.f);
                v2 = fmaxf(v2, 0.f); v3 = fmaxf(v3, 0.f);
            }
            if (r0 < M) *(float2*)(C + (size_t)r0 * 128 + c) = make_float2(v0, v1);
            if (r1 < M) *(float2*)(C + (size_t)r1 * 128 + c) = make_float2(v2, v3);
        }
    }
}

__global__ __launch_bounds__(256, 2) void k_gemm_hyb(
    const float* __restrict__ A, const float* __restrict__ W,
    const float* __restrict__ bias, int useDinv, int doRelu,
    float* __restrict__ C, int M, int K)
{
    __shared__ __align__(16) char smraw[SM_BYTES];
    const int row0 = blockIdx.x * 128;
    if (blockIdx.x & 1)
        gemm_tile_mma(A, W, bias, useDinv, doRelu, C, M, K, row0, smraw);
    else
        gemm_tile_f32(A, W, bias, useDinv, doRelu, C, M, K, row0, smraw);
}

// ---------------- CSR aggregation: y[n] = relu(dinv[n]*(g[n] + sum g[src])) ----------------
__global__ void k_aggregate(const float* __restrict__ g, float* __restrict__ y, int Nn) {
    int t = blockIdx.x * blockDim.x + threadIdx.x;
    int node = t >> 5;
    int lane = t & 31;
    if (node >= Nn) return;

    const float* gl = g + lane * 4;
    float4 acc = *(const float4*)(g + (size_t)node * HID + lane * 4);  // self loop term

    int i = d_off[node];
    int e = d_off[node + 1];
    for (; i + 4 <= e; i += 4) {
        int s0 = d_csr[i], s1 = d_csr[i + 1], s2 = d_csr[i + 2], s3 = d_csr[i + 3];
        float4 v0 = *(const float4*)(gl + (size_t)s0 * HID);
        float4 v1 = *(const float4*)(gl + (size_t)s1 * HID);
        float4 v2 = *(const float4*)(gl + (size_t)s2 * HID);
        float4 v3 = *(const float4*)(gl + (size_t)s3 * HID);
        acc.x += v0.x; acc.y += v0.y; acc.z += v0.z; acc.w += v0.w;
        acc.x += v1.x; acc.y += v1.y; acc.z += v1.z; acc.w += v1.w;
        acc.x += v2.x; acc.y += v2.y; acc.z += v2.z; acc.w += v2.w;
        acc.x += v3.x; acc.y += v3.y; acc.z += v3.z; acc.w += v3.w;
    }
    for (; i < e; i++) {
        int s = d_csr[i];
        float4 v = *(const float4*)(gl + (size_t)s * HID);
        acc.x += v.x; acc.y += v.y; acc.z += v.z; acc.w += v.w;
    }

    float dv = d_dinv[node];
    acc.x = fmaxf(acc.x * dv, 0.0f);
    acc.y = fmaxf(acc.y * dv, 0.0f);
    acc.z = fmaxf(acc.z * dv, 0.0f);
    acc.w = fmaxf(acc.w * dv, 0.0f);
    *(float4*)(y + (size_t)node * HID + lane * 4) = acc;
}

// ---------------- fc3 + log_softmax fused: 16 rows x 64 cols per 1024-thread block ----------------
__global__ __launch_bounds__(1024) void k_fc3_lsm(
    const float* __restrict__ yin, const float* __restrict__ W,
    const float* __restrict__ b, float* __restrict__ out, int Nn)
{
    __shared__ float Wsh[HID * NCLS];   // 32 KB
    __shared__ float ysh[16][HID];      // 8 KB
    __shared__ float red[16][NCLS];     // 4 KB

    int tid = threadIdx.x;
    for (int i = tid; i < HID * NCLS; i += 1024) Wsh[i] = W[i];

    int rr = tid >> 6;       // 0..15
    int c  = tid & 63;
    int row = blockIdx.x * 16 + rr;
    bool valid = row < Nn;

    if (valid) {
        ysh[rr][c]      = yin[(size_t)row * HID + c];
        ysh[rr][c + 64] = yin[(size_t)row * HID + 64 + c];
    } else {
        ysh[rr][c] = 0.0f; ysh[rr][c + 64] = 0.0f;
    }
    __syncthreads();

    float z = b[c];
#pragma unroll 8
    for (int k = 0; k < HID; k++) z += ysh[rr][k] * Wsh[k * NCLS + c];

    red[rr][c] = z;
    __syncthreads();
    for (int s = 32; s >= 1; s >>= 1) {
        if (c < s) red[rr][c] = fmaxf(red[rr][c], red[rr][c + s]);
        __syncthreads();
    }
    float m = red[rr][0];
    __syncthreads();

    red[rr][c] = expf(z - m);
    __syncthreads();
    for (int s = 32; s >= 1; s >>= 1) {
        if (c < s) red[rr][c] += red[rr][c + s];
        __syncthreads();
    }
    float lse = logf(red[rr][0]);

    if (valid) out[(size_t)row * NCLS + c] = z - m - lse;
}

// ---------------- launch ----------------
extern "C" void kernel_launch(void* const* d_in, const int* in_sizes, int n_in,
                              void* d_out, int out_size)
{
    const float* x    = (const float*)d_in[0];
    const int*   ei   = (const int*)d_in[1];
    const float* W0   = (const float*)d_in[2];
    const float* b0   = (const float*)d_in[3];
    const float* W1   = (const float*)d_in[4];
    const float* b1   = (const float*)d_in[5];
    const float* W2   = (const float*)d_in[6];
    const float* b2   = (const float*)d_in[7];
    const float* fc1w = (const float*)d_in[8];
    const float* fc1b = (const float*)d_in[9];
    const float* fc2w = (const float*)d_in[10];
    const float* fc2b = (const float*)d_in[11];
    const float* fc3w = (const float*)d_in[12];
    const float* fc3b = (const float*)d_in[13];
    float* out = (float*)d_out;

    const int N = in_sizes[0] / F_IN;
    const int E = in_sizes[1] / 2;
    const int* src = ei;       // edge_index[0]
    const int* dst = ei + E;   // edge_index[1]

    float *g, *y;
    cudaGetSymbolAddress((void**)&g, d_gbuf);
    cudaGetSymbolAddress((void**)&y, d_ybuf);

    const int T = 256;
    int gN  = (N + T - 1) / T;
    int gE  = (E + T - 1) / T;
    int nb  = (N + 1023) / 1024;
    int gM  = (N + 127) / 128;
    int gAg = (N * 32 + T - 1) / T;
    int gFc = (N + 15) / 16;

    // Launch order puts the L0 GEMM at position #4: every profiled round so far
    // captured launch #4, so this finally profiles the hot kernel.
    k_zero<<<gN, T>>>(N);                                 // 1
    k_count<<<gE, T>>>(dst, E);                           // 2
    k_scan1<<<nb, 1024>>>(N);                             // 3 (deg scan + dinv)
    k_gemm_hyb<<<gM, T>>>(x, W0, b0, 1, 0, g, N, F_IN);   // 4  <- profiled (needs only dinv)
    k_scan2<<<1, 1>>>(nb);                                // 5
    k_scan3<<<nb, 1024>>>(N, E);                          // 6
    k_scatter<<<gE, T>>>(src, dst, E);                    // 7
    k_aggregate<<<gAg, T>>>(g, y, N);                     // 8
    // conv1
    k_gemm_hyb<<<gM, T>>>(y, W1, b1, 1, 0, g, N, HID);
    k_aggregate<<<gAg, T>>>(g, y, N);
    // conv2
    k_gemm_hyb<<<gM, T>>>(y, W2, b2, 1, 0, g, N, HID);
    k_aggregate<<<gAg, T>>>(g, y, N);
    // fc1, fc2
    k_gemm_hyb<<<gM, T>>>(y, fc1w, fc1b, 0, 1, g, N, HID);
    k_gemm_hyb<<<gM, T>>>(g, fc2w, fc2b, 0, 1, y, N, HID);
    // fc3 + log_softmax
    k_fc3_lsm<<<gFc, 1024>>>(y, fc3w, fc3b, out, N);
}